// round 5
// baseline (speedup 1.0000x reference)
#include <cuda_runtime.h>
#include <cstdint>

// DipolePredictorE3NN — R5: hybrid TMA(feats) + LDG(coors), 2 batches/CTA.
//   d_in[0] feats [B,N,7] f32 | d_in[1] coors [B,N,3] f32 | d_in[2] adj (UNUSED)
//   d_in[3] W_tp[7] | d_in[4] W1[128,3] | d_in[5] b1[128] | d_in[6] W2[3,128] | d_in[7] b2[3]
// Output: [B,3] f32

#define NS 7
#define HID 128
#define THREADS 128
#define N_FIXED 512
#define FEATS_BYTES (N_FIXED * NS * 4)   // 14336 per batch
#define HALF_FEATS  (FEATS_BYTES / 2)    // 7168

__device__ __forceinline__ uint32_t smem_u32(const void* p) {
    uint32_t a;
    asm("{ .reg .u64 t; cvta.to.shared.u64 t, %1; cvt.u32.u64 %0, t; }"
        : "=r"(a) : "l"(p));
    return a;
}

__device__ __forceinline__ void mbar_wait0(uint32_t mbar) {
    uint32_t done;
    asm volatile(
        "{ .reg .pred p; mbarrier.try_wait.parity.shared.b64 p, [%1], 0; "
        "selp.b32 %0, 1, 0, p; }"
        : "=r"(done) : "r"(mbar) : "memory");
    if (!done) {
        asm volatile(
            "{ .reg .pred P1;\n"
            "W_%=: mbarrier.try_wait.parity.shared.b64 P1, [%0], 0, 0x989680;\n"
            "@P1 bra.uni D_%=;\n"
            "bra.uni W_%=;\n"
            "D_%=: }"
            :: "r"(mbar) : "memory");
    }
}

// Block-reduce 3-vector; warp0 runs the 3->128->3 MLP and writes out[b].
__device__ __forceinline__ void reduce_and_mlp(
    float ax, float ay, float az, int N,
    const float* __restrict__ W1, const float* __restrict__ b1,
    const float* __restrict__ W2, const float* __restrict__ b2,
    float* __restrict__ out, int b)
{
    const int lane = threadIdx.x & 31;
    const int wid  = threadIdx.x >> 5;
    __shared__ float sx[THREADS / 32], sy[THREADS / 32], sz[THREADS / 32];
    __syncthreads();   // protect smem reuse across successive calls
#pragma unroll
    for (int o = 16; o > 0; o >>= 1) {
        ax += __shfl_down_sync(0xFFFFFFFFu, ax, o);
        ay += __shfl_down_sync(0xFFFFFFFFu, ay, o);
        az += __shfl_down_sync(0xFFFFFFFFu, az, o);
    }
    if (lane == 0) { sx[wid] = ax; sy[wid] = ay; sz[wid] = az; }
    __syncthreads();
    if (wid == 0) {
        constexpr int NW = THREADS / 32;
        float rx = (lane < NW) ? sx[lane] : 0.f;
        float ry = (lane < NW) ? sy[lane] : 0.f;
        float rz = (lane < NW) ? sz[lane] : 0.f;
#pragma unroll
        for (int o = NW >> 1; o > 0; o >>= 1) {
            rx += __shfl_down_sync(0xFFFFFFFFu, rx, o);
            ry += __shfl_down_sync(0xFFFFFFFFu, ry, o);
            rz += __shfl_down_sync(0xFFFFFFFFu, rz, o);
        }
        const float scale = 0.3779644730092272f / (float)N;  // 1/sqrt(7)/N
        float g0 = __shfl_sync(0xFFFFFFFFu, rx, 0) * scale;
        float g1 = __shfl_sync(0xFFFFFFFFu, ry, 0) * scale;
        float g2 = __shfl_sync(0xFFFFFFFFu, rz, 0) * scale;
        float o0 = 0.f, o1 = 0.f, o2 = 0.f;
#pragma unroll
        for (int r = 0; r < HID / 32; r++) {
            int j = lane + r * 32;
            float h = fmaf(W1[j * 3 + 0], g0,
                      fmaf(W1[j * 3 + 1], g1,
                      fmaf(W1[j * 3 + 2], g2, b1[j])));
            h = fmaxf(h, 0.f);
            o0 = fmaf(W2[0 * HID + j], h, o0);
            o1 = fmaf(W2[1 * HID + j], h, o1);
            o2 = fmaf(W2[2 * HID + j], h, o2);
        }
#pragma unroll
        for (int o = 16; o > 0; o >>= 1) {
            o0 += __shfl_down_sync(0xFFFFFFFFu, o0, o);
            o1 += __shfl_down_sync(0xFFFFFFFFu, o1, o);
            o2 += __shfl_down_sync(0xFFFFFFFFu, o2, o);
        }
        if (lane == 0) {
            out[b * 3 + 0] = o0 + b2[0];
            out[b * 3 + 1] = o1 + b2[1];
            out[b * 3 + 2] = o2 + b2[2];
        }
    }
}

// Compute a batch's 3-vector partial sums from smem feats + register coors.
__device__ __forceinline__ void batch_accum(
    const float* __restrict__ sfeats, const float* __restrict__ w,
    const float cc[12], float& ax, float& ay, float& az)
{
    const int g = threadIdx.x;  // one float4-group of 4 nodes per thread
    const float4* f4 = reinterpret_cast<const float4*>(sfeats + g * 4 * NS);
    float ff[28];
#pragma unroll
    for (int i = 0; i < 7; i++) {
        float4 v = f4[i];
        ff[i * 4 + 0] = v.x; ff[i * 4 + 1] = v.y;
        ff[i * 4 + 2] = v.z; ff[i * 4 + 3] = v.w;
    }
#pragma unroll
    for (int j = 0; j < 4; j++) {
        float s = 0.f;
#pragma unroll
        for (int i = 0; i < NS; i++) s = fmaf(ff[j * NS + i], w[i], s);
        ax = fmaf(s, cc[j * 3 + 0], ax);
        ay = fmaf(s, cc[j * 3 + 1], ay);
        az = fmaf(s, cc[j * 3 + 2], az);
    }
}

// ---------- fast path: N==512, B even. CTA i handles batches 2i, 2i+1 ----------
__global__ __launch_bounds__(THREADS)
void dipole_hybrid_kernel(const float* __restrict__ feats,
                          const float* __restrict__ coors,
                          const float* __restrict__ W_tp,
                          const float* __restrict__ W1,
                          const float* __restrict__ b1,
                          const float* __restrict__ W2,
                          const float* __restrict__ b2,
                          float* __restrict__ out)
{
    __shared__ __align__(16) float s_feats0[N_FIXED * NS];
    __shared__ __align__(16) float s_feats1[N_FIXED * NS];
    __shared__ __align__(8)  uint64_t s_mbar[2];

    const int b0  = blockIdx.x * 2;
    const int b1i = b0 + 1;
    const int tid = threadIdx.x;

    const uint32_t mb0 = smem_u32(&s_mbar[0]);
    const uint32_t mb1 = smem_u32(&s_mbar[1]);

    if (tid == 0) {
        asm volatile("mbarrier.init.shared.b64 [%0], 1;" :: "r"(mb0) : "memory");
        asm volatile("mbarrier.init.shared.b64 [%0], 1;" :: "r"(mb1) : "memory");
    }
    __syncthreads();

    if (tid == 0) {
        // Issue ALL feats copies up front: 2 halves per batch, per-batch mbarrier.
        asm volatile("mbarrier.arrive.expect_tx.shared.b64 _, [%0], %1;"
                     :: "r"(mb0), "r"((uint32_t)FEATS_BYTES) : "memory");
        asm volatile("mbarrier.arrive.expect_tx.shared.b64 _, [%0], %1;"
                     :: "r"(mb1), "r"((uint32_t)FEATS_BYTES) : "memory");
        const char* gf0 = (const char*)(feats + (size_t)b0  * N_FIXED * NS);
        const char* gf1 = (const char*)(feats + (size_t)b1i * N_FIXED * NS);
        uint32_t sf0 = smem_u32(s_feats0);
        uint32_t sf1 = smem_u32(s_feats1);
#pragma unroll
        for (int h = 0; h < 2; h++) {
            asm volatile(
                "cp.async.bulk.shared::cta.global.mbarrier::complete_tx::bytes "
                "[%0], [%1], %2, [%3];"
                :: "r"(sf0 + h * HALF_FEATS), "l"(gf0 + h * HALF_FEATS),
                   "r"((uint32_t)HALF_FEATS), "r"(mb0) : "memory");
        }
#pragma unroll
        for (int h = 0; h < 2; h++) {
            asm volatile(
                "cp.async.bulk.shared::cta.global.mbarrier::complete_tx::bytes "
                "[%0], [%1], %2, [%3];"
                :: "r"(sf1 + h * HALF_FEATS), "l"(gf1 + h * HALF_FEATS),
                   "r"((uint32_t)HALF_FEATS), "r"(mb1) : "memory");
        }
    }

    // While TMA streams feats: load coors for BOTH batches via LDG.128 (other path),
    // and TP weights.
    float w[NS];
#pragma unroll
    for (int i = 0; i < NS; i++) w[i] = __ldg(&W_tp[i]);

    float cc0[12], cc1[12];
    {
        const float4* c0 = reinterpret_cast<const float4*>(
            coors + (size_t)b0 * N_FIXED * 3) + tid * 3;
        const float4* c1 = reinterpret_cast<const float4*>(
            coors + (size_t)b1i * N_FIXED * 3) + tid * 3;
#pragma unroll
        for (int i = 0; i < 3; i++) {
            float4 v = __ldg(&c0[i]);
            cc0[i * 4 + 0] = v.x; cc0[i * 4 + 1] = v.y;
            cc0[i * 4 + 2] = v.z; cc0[i * 4 + 3] = v.w;
        }
#pragma unroll
        for (int i = 0; i < 3; i++) {
            float4 v = __ldg(&c1[i]);
            cc1[i * 4 + 0] = v.x; cc1[i * 4 + 1] = v.y;
            cc1[i * 4 + 2] = v.z; cc1[i * 4 + 3] = v.w;
        }
    }

    // Batch 0
    mbar_wait0(mb0);
    float ax = 0.f, ay = 0.f, az = 0.f;
    batch_accum(s_feats0, w, cc0, ax, ay, az);
    reduce_and_mlp(ax, ay, az, N_FIXED, W1, b1, W2, b2, out, b0);

    // Batch 1
    mbar_wait0(mb1);
    ax = 0.f; ay = 0.f; az = 0.f;
    batch_accum(s_feats1, w, cc1, ax, ay, az);
    reduce_and_mlp(ax, ay, az, N_FIXED, W1, b1, W2, b2, out, b1i);
}

// ---------- generic fallback (any N, any B) ----------
__global__ __launch_bounds__(THREADS)
void dipole_ldg_kernel(const float* __restrict__ feats,
                       const float* __restrict__ coors,
                       const float* __restrict__ W_tp,
                       const float* __restrict__ W1,
                       const float* __restrict__ b1,
                       const float* __restrict__ W2,
                       const float* __restrict__ b2,
                       float* __restrict__ out,
                       int N)
{
    const int b   = blockIdx.x;
    const int tid = threadIdx.x;
    float w[NS];
#pragma unroll
    for (int i = 0; i < NS; i++) w[i] = __ldg(&W_tp[i]);
    const float* fb = feats + (size_t)b * N * NS;
    const float* cb = coors + (size_t)b * N * 3;
    float ax = 0.f, ay = 0.f, az = 0.f;
    for (int n = tid; n < N; n += THREADS) {
        const float* fr = fb + (size_t)n * NS;
        float s = 0.f;
#pragma unroll
        for (int i = 0; i < NS; i++) s = fmaf(fr[i], w[i], s);
        const float* cr = cb + (size_t)n * 3;
        ax = fmaf(s, cr[0], ax);
        ay = fmaf(s, cr[1], ay);
        az = fmaf(s, cr[2], az);
    }
    reduce_and_mlp(ax, ay, az, N, W1, b1, W2, b2, out, b);
}

extern "C" void kernel_launch(void* const* d_in, const int* in_sizes, int n_in,
                              void* d_out, int out_size)
{
    const float* feats = (const float*)d_in[0];
    const float* coors = (const float*)d_in[1];
    // d_in[2] = adj_mat, intentionally unused
    const float* W_tp  = (const float*)d_in[3];
    const float* W1    = (const float*)d_in[4];
    const float* b1    = (const float*)d_in[5];
    const float* W2    = (const float*)d_in[6];
    const float* b2    = (const float*)d_in[7];
    float* out = (float*)d_out;

    const int B = out_size / 3;           // output [B,3]
    const int N = in_sizes[1] / (B * 3);  // coors [B,N,3]

    if (N == N_FIXED && (B % 2) == 0) {
        dipole_hybrid_kernel<<<B / 2, THREADS>>>(feats, coors, W_tp, W1, b1, W2, b2, out);
    } else {
        dipole_ldg_kernel<<<B, THREADS>>>(feats, coors, W_tp, W1, b1, W2, b2, out, N);
    }
}

// round 6
// speedup vs baseline: 1.0195x; 1.0195x over previous
#include <cuda_runtime.h>
#include <cstdint>

// DipolePredictorE3NN — R6: dual-path probe. Even CTAs stream feats via TMA
// bulk-copy; odd CTAs stream feats via register LDG.128 (deep MLP). Coors via
// LDG everywhere. Tests whether per-SM in-flight caps are per-path.
//   d_in[0] feats [B,N,7] f32 | d_in[1] coors [B,N,3] f32 | d_in[2] adj (UNUSED)
//   d_in[3] W_tp[7] | d_in[4] W1[128,3] | d_in[5] b1[128] | d_in[6] W2[3,128] | d_in[7] b2[3]
// Output: [B,3] f32

#define NS 7
#define HID 128
#define THREADS 128
#define N_FIXED 512
#define FEATS_BYTES (N_FIXED * NS * 4)   // 14336

__device__ __forceinline__ uint32_t smem_u32(const void* p) {
    uint32_t a;
    asm("{ .reg .u64 t; cvta.to.shared.u64 t, %1; cvt.u32.u64 %0, t; }"
        : "=r"(a) : "l"(p));
    return a;
}

__device__ __forceinline__ void mbar_wait0(uint32_t mbar) {
    uint32_t done;
    asm volatile(
        "{ .reg .pred p; mbarrier.try_wait.parity.shared.b64 p, [%1], 0; "
        "selp.b32 %0, 1, 0, p; }"
        : "=r"(done) : "r"(mbar) : "memory");
    if (!done) {
        asm volatile(
            "{ .reg .pred P1;\n"
            "W_%=: mbarrier.try_wait.parity.shared.b64 P1, [%0], 0, 0x989680;\n"
            "@P1 bra.uni D_%=;\n"
            "bra.uni W_%=;\n"
            "D_%=: }"
            :: "r"(mbar) : "memory");
    }
}

// Block-reduce 3-vector; warp0 runs the 3->128->3 MLP and writes out[b].
__device__ __forceinline__ void reduce_and_mlp(
    float ax, float ay, float az, int N,
    const float* __restrict__ W1, const float* __restrict__ b1,
    const float* __restrict__ W2, const float* __restrict__ b2,
    float* __restrict__ out, int b)
{
    const int lane = threadIdx.x & 31;
    const int wid  = threadIdx.x >> 5;
    __shared__ float sx[THREADS / 32], sy[THREADS / 32], sz[THREADS / 32];
#pragma unroll
    for (int o = 16; o > 0; o >>= 1) {
        ax += __shfl_down_sync(0xFFFFFFFFu, ax, o);
        ay += __shfl_down_sync(0xFFFFFFFFu, ay, o);
        az += __shfl_down_sync(0xFFFFFFFFu, az, o);
    }
    if (lane == 0) { sx[wid] = ax; sy[wid] = ay; sz[wid] = az; }
    __syncthreads();
    if (wid == 0) {
        constexpr int NW = THREADS / 32;
        float rx = (lane < NW) ? sx[lane] : 0.f;
        float ry = (lane < NW) ? sy[lane] : 0.f;
        float rz = (lane < NW) ? sz[lane] : 0.f;
#pragma unroll
        for (int o = NW >> 1; o > 0; o >>= 1) {
            rx += __shfl_down_sync(0xFFFFFFFFu, rx, o);
            ry += __shfl_down_sync(0xFFFFFFFFu, ry, o);
            rz += __shfl_down_sync(0xFFFFFFFFu, rz, o);
        }
        const float scale = 0.3779644730092272f / (float)N;  // 1/sqrt(7)/N
        float g0 = __shfl_sync(0xFFFFFFFFu, rx, 0) * scale;
        float g1 = __shfl_sync(0xFFFFFFFFu, ry, 0) * scale;
        float g2 = __shfl_sync(0xFFFFFFFFu, rz, 0) * scale;
        float o0 = 0.f, o1 = 0.f, o2 = 0.f;
#pragma unroll
        for (int r = 0; r < HID / 32; r++) {
            int j = lane + r * 32;
            float h = fmaf(W1[j * 3 + 0], g0,
                      fmaf(W1[j * 3 + 1], g1,
                      fmaf(W1[j * 3 + 2], g2, b1[j])));
            h = fmaxf(h, 0.f);
            o0 = fmaf(W2[0 * HID + j], h, o0);
            o1 = fmaf(W2[1 * HID + j], h, o1);
            o2 = fmaf(W2[2 * HID + j], h, o2);
        }
#pragma unroll
        for (int o = 16; o > 0; o >>= 1) {
            o0 += __shfl_down_sync(0xFFFFFFFFu, o0, o);
            o1 += __shfl_down_sync(0xFFFFFFFFu, o1, o);
            o2 += __shfl_down_sync(0xFFFFFFFFu, o2, o);
        }
        if (lane == 0) {
            out[b * 3 + 0] = o0 + b2[0];
            out[b * 3 + 1] = o1 + b2[1];
            out[b * 3 + 2] = o2 + b2[2];
        }
    }
}

// ---------- fast path: N==512. CTA parity selects feats transport ----------
__global__ __launch_bounds__(THREADS, 1)
void dipole_dual_kernel(const float* __restrict__ feats,
                        const float* __restrict__ coors,
                        const float* __restrict__ W_tp,
                        const float* __restrict__ W1,
                        const float* __restrict__ b1,
                        const float* __restrict__ W2,
                        const float* __restrict__ b2,
                        float* __restrict__ out)
{
    __shared__ __align__(16) float s_feats[N_FIXED * NS];  // used by even CTAs only
    __shared__ __align__(8)  uint64_t s_mbar;

    const int b    = blockIdx.x;
    const int tid  = threadIdx.x;
    const bool use_tma = ((b & 1) == 0);

    const uint32_t mbar = smem_u32(&s_mbar);
    if (use_tma) {
        if (tid == 0) {
            asm volatile("mbarrier.init.shared.b64 [%0], 1;" :: "r"(mbar) : "memory");
        }
        __syncthreads();
        if (tid == 0) {
            asm volatile("mbarrier.arrive.expect_tx.shared.b64 _, [%0], %1;"
                         :: "r"(mbar), "r"((uint32_t)FEATS_BYTES) : "memory");
            const char* gf = (const char*)(feats + (size_t)b * N_FIXED * NS);
            asm volatile(
                "cp.async.bulk.shared::cta.global.mbarrier::complete_tx::bytes "
                "[%0], [%1], %2, [%3];"
                :: "r"(smem_u32(s_feats)), "l"(gf), "r"((uint32_t)FEATS_BYTES),
                   "r"(mbar) : "memory");
        }
    }

    // Common: TP weights + coors via LDG.128 (issued while TMA in flight on even CTAs)
    float w[NS];
#pragma unroll
    for (int i = 0; i < NS; i++) w[i] = __ldg(&W_tp[i]);

    float4 cc4[3];
    {
        const float4* c4 = reinterpret_cast<const float4*>(
            coors + (size_t)b * N_FIXED * 3) + tid * 3;
#pragma unroll
        for (int i = 0; i < 3; i++) cc4[i] = __ldg(&c4[i]);
    }
    const float* cc = reinterpret_cast<const float*>(cc4);

    float ax = 0.f, ay = 0.f, az = 0.f;

    if (use_tma) {
        mbar_wait0(mbar);
        const float4* f4s = reinterpret_cast<const float4*>(s_feats) + tid * 7;
        float4 ff4[7];
#pragma unroll
        for (int i = 0; i < 7; i++) ff4[i] = f4s[i];
        const float* ff = reinterpret_cast<const float*>(ff4);
#pragma unroll
        for (int j = 0; j < 4; j++) {
            float s = 0.f;
#pragma unroll
            for (int i = 0; i < NS; i++) s = fmaf(ff[j * NS + i], w[i], s);
            ax = fmaf(s, cc[j * 3 + 0], ax);
            ay = fmaf(s, cc[j * 3 + 1], ay);
            az = fmaf(s, cc[j * 3 + 2], az);
        }
    } else {
        // Deep-MLP LDG path: all 7 feats LDG.128 issued back-to-back.
        const float4* f4g = reinterpret_cast<const float4*>(
            feats + (size_t)b * N_FIXED * NS) + tid * 7;
        float4 ff4[7];
#pragma unroll
        for (int i = 0; i < 7; i++) ff4[i] = __ldg(&f4g[i]);
        const float* ff = reinterpret_cast<const float*>(ff4);
#pragma unroll
        for (int j = 0; j < 4; j++) {
            float s = 0.f;
#pragma unroll
            for (int i = 0; i < NS; i++) s = fmaf(ff[j * NS + i], w[i], s);
            ax = fmaf(s, cc[j * 3 + 0], ax);
            ay = fmaf(s, cc[j * 3 + 1], ay);
            az = fmaf(s, cc[j * 3 + 2], az);
        }
    }

    __syncthreads();
    reduce_and_mlp(ax, ay, az, N_FIXED, W1, b1, W2, b2, out, b);
}

// ---------- generic fallback (any N) ----------
__global__ __launch_bounds__(THREADS)
void dipole_ldg_kernel(const float* __restrict__ feats,
                       const float* __restrict__ coors,
                       const float* __restrict__ W_tp,
                       const float* __restrict__ W1,
                       const float* __restrict__ b1,
                       const float* __restrict__ W2,
                       const float* __restrict__ b2,
                       float* __restrict__ out,
                       int N)
{
    const int b   = blockIdx.x;
    const int tid = threadIdx.x;
    float w[NS];
#pragma unroll
    for (int i = 0; i < NS; i++) w[i] = __ldg(&W_tp[i]);
    const float* fb = feats + (size_t)b * N * NS;
    const float* cb = coors + (size_t)b * N * 3;
    float ax = 0.f, ay = 0.f, az = 0.f;
    for (int n = tid; n < N; n += THREADS) {
        const float* fr = fb + (size_t)n * NS;
        float s = 0.f;
#pragma unroll
        for (int i = 0; i < NS; i++) s = fmaf(fr[i], w[i], s);
        const float* cr = cb + (size_t)n * 3;
        ax = fmaf(s, cr[0], ax);
        ay = fmaf(s, cr[1], ay);
        az = fmaf(s, cr[2], az);
    }
    __syncthreads();
    reduce_and_mlp(ax, ay, az, N, W1, b1, W2, b2, out, b);
}

extern "C" void kernel_launch(void* const* d_in, const int* in_sizes, int n_in,
                              void* d_out, int out_size)
{
    const float* feats = (const float*)d_in[0];
    const float* coors = (const float*)d_in[1];
    // d_in[2] = adj_mat, intentionally unused
    const float* W_tp  = (const float*)d_in[3];
    const float* W1    = (const float*)d_in[4];
    const float* b1    = (const float*)d_in[5];
    const float* W2    = (const float*)d_in[6];
    const float* b2    = (const float*)d_in[7];
    float* out = (float*)d_out;

    const int B = out_size / 3;           // output [B,3]
    const int N = in_sizes[1] / (B * 3);  // coors [B,N,3]

    if (N == N_FIXED) {
        dipole_dual_kernel<<<B, THREADS>>>(feats, coors, W_tp, W1, b1, W2, b2, out);
    } else {
        dipole_ldg_kernel<<<B, THREADS>>>(feats, coors, W_tp, W1, b1, W2, b2, out, N);
    }
}